// round 6
// baseline (speedup 1.0000x reference)
#include <cuda_runtime.h>

#define BB   16
#define TT   4096
#define FEAT 256
#define KW   5
#define CH   64            // seq_scan chunk (steps)
#define GRP  16            // checkpoint group
#define NGRP (TT / GRP)    // 256 groups per batch

// Scratch (no allocations allowed).
__device__ float  g_weff[FEAT * KW];
__device__ float  g_bias;
__device__ float  g_alphas[BB * TT];     // [b][t] for emit/compact
__device__ float  g_alphasT[TT * BB];    // [t][b] for seq_scan (coalesced)
__device__ float  g_chk[NGRP * BB];      // acc checkpoint before each 16-group
__device__ float  g_accb[TT * BB];       // acc BEFORE step t (filled by compact)
__device__ int    g_ft[BB * TT];
__device__ int2   g_seg[BB * TT];
__device__ int    g_n[BB];
__device__ int    g_nofire[BB];

#define ACCB(t, b) g_accb[(t) * BB + (b)]

// ---------------------------------------------------------------------------
// Kernel 1: fold lin_w into conv_w  ->  w_eff[c,k] = sum_o lin_w[o]*conv_w[o,c,k]
// ---------------------------------------------------------------------------
__global__ void fold_kernel(const float* __restrict__ conv_w,
                            const float* __restrict__ conv_b,
                            const float* __restrict__ lin_w,
                            const float* __restrict__ lin_b) {
    int j = blockIdx.x * blockDim.x + threadIdx.x;   // j = c*KW + k
    if (j < FEAT * KW) {
        float s = 0.f;
#pragma unroll 4
        for (int o = 0; o < FEAT; ++o)
            s = fmaf(lin_w[o], conv_w[o * (FEAT * KW) + j], s);
        g_weff[j] = s;
    }
    if (blockIdx.x == 0) {
        __shared__ float sh[256];
        sh[threadIdx.x] = conv_b[threadIdx.x] * lin_w[threadIdx.x];
        __syncthreads();
        for (int ofs = 128; ofs > 0; ofs >>= 1) {
            if ((int)threadIdx.x < ofs) sh[threadIdx.x] += sh[threadIdx.x + ofs];
            __syncthreads();
        }
        if (threadIdx.x == 0) g_bias = sh[0] + lin_b[0];
    }
}

// ---------------------------------------------------------------------------
// Kernel 2 (fused conv+linear+sigmoid): alphas[b,t] = sigmoid(bias +
// sum_c sum_k w_eff[c,k] x[b, t+k-2, c]).  32 rows per block staged in smem
// with 2-row halo; each warp computes 4 rows: 40 FMA/lane into ONE scalar,
// 5 shfls per row, sigmoid, dual-layout store.
// ---------------------------------------------------------------------------
#define RPB 32
#define SROWS (RPB + 4)

__global__ __launch_bounds__(256) void logit_kernel(const float* __restrict__ x) {
    __shared__ float4 sx[SROWS][FEAT / 4];   // 36 KB

    int blk = blockIdx.x;                 // 0 .. BB*(TT/RPB)-1
    int b = blk >> 7;                     // TT/RPB = 128 blocks per batch
    int r0 = (blk & 127) * RPB;
    int tid = threadIdx.x;
    int lane = tid & 31;
    int w = tid >> 5;

    const float* xb = x + (size_t)b * TT * FEAT;

    // stage rows r0-2 .. r0+33 (zero outside [0,TT))
#pragma unroll
    for (int i = 0; i < SROWS; ++i) {
        int gr = r0 - 2 + i;
        float v = 0.f;
        if (gr >= 0 && gr < TT) v = xb[(size_t)gr * FEAT + tid];
        ((float*)sx[i])[tid] = v;
    }
    __syncthreads();

    // lane-owned folded weights: channels 4*lane..+3 and 128+4*lane..+3
    float wr[8][KW];
#pragma unroll
    for (int j = 0; j < 8; ++j) {
        int c = (j < 4) ? (4 * lane + j) : (124 + 4 * lane + j);
#pragma unroll
        for (int k = 0; k < KW; ++k) wr[j][k] = g_weff[c * KW + k];
    }
    float bias = g_bias;

#pragma unroll
    for (int r = 0; r < 4; ++r) {
        int j = w * 4 + r;                // local row, smem center = j+2
        float s = 0.f;
#pragma unroll
        for (int k = 0; k < KW; ++k) {
            float4 A = sx[j + k][lane];
            float4 B = sx[j + k][lane + 32];
            s = fmaf(A.x, wr[0][k], s);
            s = fmaf(A.y, wr[1][k], s);
            s = fmaf(A.z, wr[2][k], s);
            s = fmaf(A.w, wr[3][k], s);
            s = fmaf(B.x, wr[4][k], s);
            s = fmaf(B.y, wr[5][k], s);
            s = fmaf(B.z, wr[6][k], s);
            s = fmaf(B.w, wr[7][k], s);
        }
#pragma unroll
        for (int ofs = 16; ofs > 0; ofs >>= 1)
            s += __shfl_xor_sync(0xffffffffu, s, ofs);
        if (lane == 0) {
            int t = r0 + j;
            float v = 1.f / (1.f + expf(-(s + bias)));
            g_alphas[(size_t)b * TT + t] = v;
            g_alphasT[t * BB + b] = v;
        }
    }
}

// ---------------------------------------------------------------------------
// Kernel 3: sequential alpha scan — minimal body. smem double-buffered
// 64-step chunks; per step only LDS(amortized)+3xFADD+FSETP+FSEL; one
// STG.32 checkpoint per 16 steps. Everything else reconstructed by compact.
// ---------------------------------------------------------------------------
__global__ __launch_bounds__(32, 1) void seq_scan_kernel() {
    __shared__ float sa[2][CH * BB];          // 2 x 4KB
    const int lane = threadIdx.x;
    const int b = lane & 15;

    const float4* src = (const float4*)g_alphasT;

    {
        float4 v[8];
#pragma unroll
        for (int i = 0; i < 8; ++i) v[i] = src[lane + 32 * i];
#pragma unroll
        for (int i = 0; i < 8; ++i) ((float4*)sa[0])[lane + 32 * i] = v[i];
    }
    __syncwarp();

    float acc = 0.f;
    int buf = 0;

    for (int c = 0; c < TT / CH; ++c) {
        float4 pf[8];
        if (c + 1 < TT / CH) {
            const float4* s2 = src + (c + 1) * (CH * BB / 4);
#pragma unroll
            for (int i = 0; i < 8; ++i) pf[i] = s2[lane + 32 * i];
        }

        if (lane < 16) {
            const float* s = sa[buf] + b;
            float cur[16], nxt[16];
#pragma unroll
            for (int j = 0; j < 16; ++j) cur[j] = s[j * BB];
#pragma unroll
            for (int sub = 0; sub < CH / 16; ++sub) {
                if (sub + 1 < CH / 16) {
#pragma unroll
                    for (int j = 0; j < 16; ++j)
                        nxt[j] = s[(sub * 16 + 16 + j) * BB];
                }
                g_chk[(c * (CH / GRP) + sub) * BB + b] = acc;   // checkpoint
#pragma unroll
                for (int j = 0; j < 16; ++j) {
                    float a = cur[j];
                    float acc_new = acc + a;
                    float a1 = 1.0f - acc;
                    float a2 = a - a1;
                    acc = (acc_new >= 1.0f) ? a2 : acc_new;
                }
#pragma unroll
                for (int j = 0; j < 16; ++j) cur[j] = nxt[j];
            }
        }

        if (c + 1 < TT / CH) {
            buf ^= 1;
            __syncwarp();
#pragma unroll
            for (int i = 0; i < 8; ++i)
                ((float4*)sa[buf])[lane + 32 * i] = pf[i];
            __syncwarp();
        }
    }
}

// ---------------------------------------------------------------------------
// Kernel 4: compact. 256 threads/batch; thread g replays 16-step group g from
// its checkpoint with the IDENTICAL fp ops (bit-identical fire + acc), writes
// acc_before for all steps, builds masks -> prefix -> segment table.
// ---------------------------------------------------------------------------
__global__ __launch_bounds__(256) void compact_kernel(float* __restrict__ lens,
                                                      int write_len) {
    int b = blockIdx.x;
    int g = threadIdx.x;                       // 0..255
    __shared__ int tmp[256];
    __shared__ int pre0[1];

    int base = g * GRP;
    float acc = g_chk[g * BB + b];
    const float* ab = g_alphas + (size_t)b * TT + base;

    unsigned m = 0u;
#pragma unroll
    for (int j = 0; j < GRP; ++j) {
        float a = ab[j];
        g_accb[(base + j) * BB + b] = acc;
        float acc_new = acc + a;
        float a1 = 1.0f - acc;
        float a2 = a - a1;
        bool fire = (acc_new >= 1.0f);
        if (fire) m |= (1u << j);
        acc = fire ? a2 : acc_new;
    }
    int cnt = __popc(m);

    // inclusive prefix over 256 threads
    tmp[g] = cnt;
    __syncthreads();
    for (int ofs = 1; ofs < 256; ofs <<= 1) {
        int v = (g >= ofs) ? tmp[g - ofs] : 0;
        __syncthreads();
        tmp[g] += v;
        __syncthreads();
    }
    int n = tmp[255];
    int rank = tmp[g] - cnt;                   // exclusive
    const int wbase = b * TT;

    unsigned mm = m;
    while (mm) {
        int i = __ffs(mm) - 1;
        mm &= mm - 1;
        g_ft[wbase + rank] = base + i;
        ++rank;
    }
    __syncthreads();

    if (n == 0) {
        if (g == 0) {
            g_ft[wbase] = TT - 1;
            g_seg[wbase] = make_int2(-1, TT - 1);
            g_n[b] = 1;
            g_nofire[b] = 1;
            if (write_len) lens[b] = 1.0f;
        }
        return;
    }

    for (int j = g; j < n; j += 256) {
        int s = (j == 0) ? -1 : g_ft[wbase + j - 1];
        g_seg[wbase + j] = make_int2(s, g_ft[wbase + j]);
    }
    if (g == 0) {
        g_n[b] = n;
        g_nofire[b] = 0;
        if (write_len) lens[b] = (float)n;
    }
}

// ---------------------------------------------------------------------------
// Kernel 5: fused emission + tail zero. Weights recomputed from acc_before
// with the reference's exact fp ops:
//   a1(e) = 1 - acc_before[e];   a2(s) = alpha[s] - (1 - acc_before[s]).
// ---------------------------------------------------------------------------
__global__ __launch_bounds__(FEAT) void emit_kernel(const float* __restrict__ x,
                                                    float* __restrict__ out) {
    int b = blockIdx.x;
    int d = threadIdx.x;
    int n = g_n[b];
    int nofire = g_nofire[b];
    const float* xb = x + (size_t)b * TT * FEAT;
    const float* ab = g_alphas + (size_t)b * TT;
    const int wbase = b * TT;
    float* ob = out + (size_t)b * TT * FEAT;

    for (int j = blockIdx.y; j < TT; j += gridDim.y) {
        if (j >= n) {
            ob[(size_t)j * FEAT + d] = 0.f;
            continue;
        }
        int2 se = g_seg[wbase + j];
        float accv = 0.f;
        int u0 = 0;
        if (se.x >= 0) {
            float a2 = ab[se.x] - (1.0f - ACCB(se.x, b));
            accv = a2 * xb[(size_t)se.x * FEAT + d];
            u0 = se.x + 1;
        }
        for (int u = u0; u < se.y; ++u)
            accv = fmaf(ab[u], xb[(size_t)u * FEAT + d], accv);
        float we = nofire ? ab[se.y] : (1.0f - ACCB(se.y, b));
        accv = fmaf(we, xb[(size_t)se.y * FEAT + d], accv);
        ob[(size_t)j * FEAT + d] = accv;
    }
}

// ---------------------------------------------------------------------------
extern "C" void kernel_launch(void* const* d_in, const int* in_sizes, int n_in,
                              void* d_out, int out_size) {
    const float* x      = (const float*)d_in[0];
    const float* conv_w = (const float*)d_in[1];
    const float* conv_b = (const float*)d_in[2];
    const float* lin_w  = (const float*)d_in[3];
    const float* lin_b  = (const float*)d_in[4];
    float* out = (float*)d_out;

    const size_t dense = (size_t)BB * TT * FEAT;
    if ((size_t)out_size > dense)
        cudaMemsetAsync(out + dense, 0, ((size_t)out_size - dense) * sizeof(float), 0);

    fold_kernel<<<5, 256>>>(conv_w, conv_b, lin_w, lin_b);
    logit_kernel<<<BB * (TT / RPB), 256>>>(x);

    seq_scan_kernel<<<1, 32>>>();

    int write_len = (out_size >= BB * TT * FEAT + BB) ? 1 : 0;
    float* lens = out + dense;
    compact_kernel<<<BB, 256>>>(lens, write_len);

    emit_kernel<<<dim3(BB, 256), FEAT>>>(x, out);
}

// round 8
// speedup vs baseline: 1.0320x; 1.0320x over previous
#include <cuda_runtime.h>

#define BB   16
#define TT   4096
#define FEAT 256
#define KW   5
#define CH   128           // seq_scan chunk (steps)
#define GRP  16            // checkpoint group
#define NGRP (TT / GRP)    // 256 groups per batch

// Scratch (no allocations allowed).
__device__ float  g_weff[FEAT * KW];
__device__ float  g_bias;
__device__ float  g_alphas[BB * TT];     // [b][t] for emit/compact
__device__ float  g_alphasT[TT * BB];    // [t][b] for seq_scan (coalesced)
__device__ float  g_chk[NGRP * BB];      // acc checkpoint before each 16-group
__device__ float  g_accb[BB * TT];       // acc BEFORE step t, [b][t] (by compact)
__device__ int    g_ft[BB * TT];
__device__ int2   g_seg[BB * TT];
__device__ int    g_n[BB];
__device__ int    g_nofire[BB];

#define ACCB(t, b) g_accb[(size_t)(b) * TT + (t)]

// ---------------------------------------------------------------------------
// Kernel 1: fold lin_w into conv_w  ->  w_eff[c,k] = sum_o lin_w[o]*conv_w[o,c,k]
// ---------------------------------------------------------------------------
__global__ void fold_kernel(const float* __restrict__ conv_w,
                            const float* __restrict__ conv_b,
                            const float* __restrict__ lin_w,
                            const float* __restrict__ lin_b) {
    int j = blockIdx.x * blockDim.x + threadIdx.x;   // j = c*KW + k
    if (j < FEAT * KW) {
        float s = 0.f;
#pragma unroll 4
        for (int o = 0; o < FEAT; ++o)
            s = fmaf(lin_w[o], conv_w[o * (FEAT * KW) + j], s);
        g_weff[j] = s;
    }
    if (blockIdx.x == 0) {
        __shared__ float sh[256];
        sh[threadIdx.x] = conv_b[threadIdx.x] * lin_w[threadIdx.x];
        __syncthreads();
        for (int ofs = 128; ofs > 0; ofs >>= 1) {
            if ((int)threadIdx.x < ofs) sh[threadIdx.x] += sh[threadIdx.x + ofs];
            __syncthreads();
        }
        if (threadIdx.x == 0) g_bias = sh[0] + lin_b[0];
    }
}

// ---------------------------------------------------------------------------
// Kernel 2 (fused conv+linear+sigmoid): alphas[b,t] = sigmoid(bias +
// sum_c sum_k w_eff[c,k] x[b, t+k-2, c]).
// ---------------------------------------------------------------------------
#define RPB 32
#define SROWS (RPB + 4)

__global__ __launch_bounds__(256) void logit_kernel(const float* __restrict__ x) {
    __shared__ float4 sx[SROWS][FEAT / 4];   // 36 KB

    int blk = blockIdx.x;                 // 0 .. BB*(TT/RPB)-1
    int b = blk >> 7;                     // TT/RPB = 128 blocks per batch
    int r0 = (blk & 127) * RPB;
    int tid = threadIdx.x;
    int lane = tid & 31;
    int w = tid >> 5;

    const float* xb = x + (size_t)b * TT * FEAT;

#pragma unroll
    for (int i = 0; i < SROWS; ++i) {
        int gr = r0 - 2 + i;
        float v = 0.f;
        if (gr >= 0 && gr < TT) v = xb[(size_t)gr * FEAT + tid];
        ((float*)sx[i])[tid] = v;
    }
    __syncthreads();

    float wr[8][KW];
#pragma unroll
    for (int j = 0; j < 8; ++j) {
        int c = (j < 4) ? (4 * lane + j) : (124 + 4 * lane + j);
#pragma unroll
        for (int k = 0; k < KW; ++k) wr[j][k] = g_weff[c * KW + k];
    }
    float bias = g_bias;

#pragma unroll
    for (int r = 0; r < 4; ++r) {
        int j = w * 4 + r;
        float s = 0.f;
#pragma unroll
        for (int k = 0; k < KW; ++k) {
            float4 A = sx[j + k][lane];
            float4 B = sx[j + k][lane + 32];
            s = fmaf(A.x, wr[0][k], s);
            s = fmaf(A.y, wr[1][k], s);
            s = fmaf(A.z, wr[2][k], s);
            s = fmaf(A.w, wr[3][k], s);
            s = fmaf(B.x, wr[4][k], s);
            s = fmaf(B.y, wr[5][k], s);
            s = fmaf(B.z, wr[6][k], s);
            s = fmaf(B.w, wr[7][k], s);
        }
#pragma unroll
        for (int ofs = 16; ofs > 0; ofs >>= 1)
            s += __shfl_xor_sync(0xffffffffu, s, ofs);
        if (lane == 0) {
            int t = r0 + j;
            float v = 1.f / (1.f + expf(-(s + bias)));
            g_alphas[(size_t)b * TT + t] = v;
            g_alphasT[t * BB + b] = v;
        }
    }
}

// ---------------------------------------------------------------------------
// Kernel 3: sequential alpha scan — minimal body. 128-step chunks double-
// buffered in smem; per step: direct LDS (immediate offset, hoisted by ptxas)
// + 3xFADD + FSETP + FSEL; one STG.32 checkpoint per 16 steps.
// ---------------------------------------------------------------------------
__global__ __launch_bounds__(32, 1) void seq_scan_kernel() {
    __shared__ float sa[2][CH * BB];          // 2 x 8KB
    const int lane = threadIdx.x;
    const int b = lane & 15;

    const float4* src = (const float4*)g_alphasT;  // CH*BB/4 = 512 float4/chunk

    {
        float4 v[16];
#pragma unroll
        for (int i = 0; i < 16; ++i) v[i] = src[lane + 32 * i];
#pragma unroll
        for (int i = 0; i < 16; ++i) ((float4*)sa[0])[lane + 32 * i] = v[i];
    }
    __syncwarp();

    float acc = 0.f;
    int buf = 0;

    for (int c = 0; c < TT / CH; ++c) {
        float4 pf[16];
        if (c + 1 < TT / CH) {
            const float4* s2 = src + (c + 1) * (CH * BB / 4);
#pragma unroll
            for (int i = 0; i < 16; ++i) pf[i] = s2[lane + 32 * i];
        }

        if (lane < 16) {
            const float* s = sa[buf] + b;
#pragma unroll
            for (int sub = 0; sub < CH / GRP; ++sub) {
                g_chk[(c * (CH / GRP) + sub) * BB + b] = acc;   // checkpoint
#pragma unroll
                for (int j = 0; j < GRP; ++j) {
                    float a = s[(sub * GRP + j) * BB];          // LDS, imm offset
                    float acc_new = acc + a;
                    float a1 = 1.0f - acc;
                    float a2 = a - a1;
                    acc = (acc_new >= 1.0f) ? a2 : acc_new;
                }
            }
        }

        if (c + 1 < TT / CH) {
            buf ^= 1;
            __syncwarp();
#pragma unroll
            for (int i = 0; i < 16; ++i)
                ((float4*)sa[buf])[lane + 32 * i] = pf[i];
            __syncwarp();
        }
    }
}

// ---------------------------------------------------------------------------
// Kernel 4: compact. Thread g replays 16-step group g from its checkpoint
// with IDENTICAL fp ops (bit-identical fire + acc), writes acc_before
// COALESCED as 4x STG.128 into [b][t], builds masks -> prefix -> segments.
// ---------------------------------------------------------------------------
__global__ __launch_bounds__(256) void compact_kernel(float* __restrict__ lens,
                                                      int write_len) {
    int b = blockIdx.x;
    int g = threadIdx.x;                       // 0..255
    __shared__ int tmp[256];

    int base = g * GRP;
    float acc = g_chk[g * BB + b];
    const float* ab = g_alphas + (size_t)b * TT + base;

    float accs[GRP];
    unsigned m = 0u;
#pragma unroll
    for (int j = 0; j < GRP; ++j) {
        float a = ab[j];
        accs[j] = acc;
        float acc_new = acc + a;
        float a1 = 1.0f - acc;
        float a2 = a - a1;
        bool fire = (acc_new >= 1.0f);
        if (fire) m |= (1u << j);
        acc = fire ? a2 : acc_new;
    }
    // coalesced acc_before store: [b][t], 16 consecutive floats per thread
    float4* dst = (float4*)(g_accb + (size_t)b * TT + base);
#pragma unroll
    for (int q = 0; q < 4; ++q)
        dst[q] = make_float4(accs[q * 4], accs[q * 4 + 1],
                             accs[q * 4 + 2], accs[q * 4 + 3]);

    int cnt = __popc(m);
    tmp[g] = cnt;
    __syncthreads();
    for (int ofs = 1; ofs < 256; ofs <<= 1) {
        int v = (g >= ofs) ? tmp[g - ofs] : 0;
        __syncthreads();
        tmp[g] += v;
        __syncthreads();
    }
    int n = tmp[255];
    int rank = tmp[g] - cnt;                   // exclusive
    const int wbase = b * TT;

    unsigned mm = m;
    while (mm) {
        int i = __ffs(mm) - 1;
        mm &= mm - 1;
        g_ft[wbase + rank] = base + i;
        ++rank;
    }
    __syncthreads();

    if (n == 0) {
        if (g == 0) {
            g_ft[wbase] = TT - 1;
            g_seg[wbase] = make_int2(-1, TT - 1);
            g_n[b] = 1;
            g_nofire[b] = 1;
            if (write_len) lens[b] = 1.0f;
        }
        return;
    }

    for (int j = g; j < n; j += 256) {
        int s = (j == 0) ? -1 : g_ft[wbase + j - 1];
        g_seg[wbase + j] = make_int2(s, g_ft[wbase + j]);
    }
    if (g == 0) {
        g_n[b] = n;
        g_nofire[b] = 0;
        if (write_len) lens[b] = (float)n;
    }
}

// ---------------------------------------------------------------------------
// Kernel 5: fused emission + tail zero. Weights recomputed from acc_before
// with the reference's exact fp ops:
//   a1(e) = 1 - acc_before[e];   a2(s) = alpha[s] - (1 - acc_before[s]).
// ---------------------------------------------------------------------------
__global__ __launch_bounds__(FEAT) void emit_kernel(const float* __restrict__ x,
                                                    float* __restrict__ out) {
    int b = blockIdx.x;
    int d = threadIdx.x;
    int n = g_n[b];
    int nofire = g_nofire[b];
    const float* xb = x + (size_t)b * TT * FEAT;
    const float* ab = g_alphas + (size_t)b * TT;
    const int wbase = b * TT;
    float* ob = out + (size_t)b * TT * FEAT;

    for (int j = blockIdx.y; j < TT; j += gridDim.y) {
        if (j >= n) {
            ob[(size_t)j * FEAT + d] = 0.f;
            continue;
        }
        int2 se = g_seg[wbase + j];
        float accv = 0.f;
        int u0 = 0;
        if (se.x >= 0) {
            float a2 = ab[se.x] - (1.0f - ACCB(se.x, b));
            accv = a2 * xb[(size_t)se.x * FEAT + d];
            u0 = se.x + 1;
        }
        for (int u = u0; u < se.y; ++u)
            accv = fmaf(ab[u], xb[(size_t)u * FEAT + d], accv);
        float we = nofire ? ab[se.y] : (1.0f - ACCB(se.y, b));
        accv = fmaf(we, xb[(size_t)se.y * FEAT + d], accv);
        ob[(size_t)j * FEAT + d] = accv;
    }
}

// ---------------------------------------------------------------------------
extern "C" void kernel_launch(void* const* d_in, const int* in_sizes, int n_in,
                              void* d_out, int out_size) {
    const float* x      = (const float*)d_in[0];
    const float* conv_w = (const float*)d_in[1];
    const float* conv_b = (const float*)d_in[2];
    const float* lin_w  = (const float*)d_in[3];
    const float* lin_b  = (const float*)d_in[4];
    float* out = (float*)d_out;

    const size_t dense = (size_t)BB * TT * FEAT;
    if ((size_t)out_size > dense)
        cudaMemsetAsync(out + dense, 0, ((size_t)out_size - dense) * sizeof(float), 0);

    fold_kernel<<<5, 256>>>(conv_w, conv_b, lin_w, lin_b);
    logit_kernel<<<BB * (TT / RPB), 256>>>(x);

    seq_scan_kernel<<<1, 32>>>();

    int write_len = (out_size >= BB * TT * FEAT + BB) ? 1 : 0;
    float* lens = out + dense;
    compact_kernel<<<BB, 256>>>(lens, write_len);

    emit_kernel<<<dim3(BB, 256), FEAT>>>(x, out);
}